// round 3
// baseline (speedup 1.0000x reference)
#include <cuda_runtime.h>
#include <cstdint>

// Problem constants
#define BB 8
#define TT 2048
#define CC 1024
#define HH 64
#define MM (BB * TT)   // 16384 rows

// Scratch for Q, K, V projections (static device globals: allocation-free)
__device__ float g_q[MM * HH];
__device__ float g_k[MM * HH];
__device__ float g_v[MM * HH];

// ---------------------------------------------------------------------------
// Kernel 1: fused QKV projection.  grid = (MM/64, 3), block = 256.
// Standard SGEMM tile: BM=64, BN=64(=HH), BK=32, 4x4 per-thread.
// ---------------------------------------------------------------------------
__global__ __launch_bounds__(256) void proj_kernel(
    const float* __restrict__ x,
    const float* __restrict__ Wq,
    const float* __restrict__ Wk,
    const float* __restrict__ Wv)
{
    __shared__ float As[64][36];   // row-major x tile, pad to 36 (16B-aligned rows)
    __shared__ float Bs[32][64];   // W tile [k][n]

    const float* W  = (blockIdx.y == 0) ? Wq : (blockIdx.y == 1) ? Wk : Wv;
    float*       out = (blockIdx.y == 0) ? g_q : (blockIdx.y == 1) ? g_k : g_v;

    const int m0  = blockIdx.x * 64;
    const int tid = threadIdx.x;
    const int tx  = tid & 15;      // n-tile
    const int ty  = tid >> 4;      // m-tile

    float acc[4][4] = {};

    for (int k0 = 0; k0 < CC; k0 += 32) {
        // Load A tile: 64x32 = 512 float4, 2 per thread
        #pragma unroll
        for (int l = 0; l < 2; l++) {
            int idx = tid + l * 256;
            int row = idx >> 3;
            int c4  = idx & 7;
            float4 v = *(const float4*)&x[(size_t)(m0 + row) * CC + k0 + c4 * 4];
            *(float4*)&As[row][c4 * 4] = v;
        }
        // Load B tile: 32x64 = 512 float4, 2 per thread
        #pragma unroll
        for (int l = 0; l < 2; l++) {
            int idx = tid + l * 256;
            int row = idx >> 4;
            int c4  = idx & 15;
            float4 v = *(const float4*)&W[(size_t)(k0 + row) * HH + c4 * 4];
            *(float4*)&Bs[row][c4 * 4] = v;
        }
        __syncthreads();

        #pragma unroll
        for (int kk = 0; kk < 32; kk++) {
            float a0 = As[ty * 4 + 0][kk];
            float a1 = As[ty * 4 + 1][kk];
            float a2 = As[ty * 4 + 2][kk];
            float a3 = As[ty * 4 + 3][kk];
            float4 b = *(const float4*)&Bs[kk][tx * 4];
            acc[0][0] += a0 * b.x; acc[0][1] += a0 * b.y; acc[0][2] += a0 * b.z; acc[0][3] += a0 * b.w;
            acc[1][0] += a1 * b.x; acc[1][1] += a1 * b.y; acc[1][2] += a1 * b.z; acc[1][3] += a1 * b.w;
            acc[2][0] += a2 * b.x; acc[2][1] += a2 * b.y; acc[2][2] += a2 * b.z; acc[2][3] += a2 * b.w;
            acc[3][0] += a3 * b.x; acc[3][1] += a3 * b.y; acc[3][2] += a3 * b.z; acc[3][3] += a3 * b.w;
        }
        __syncthreads();
    }

    #pragma unroll
    for (int i = 0; i < 4; i++) {
        float4 v = make_float4(acc[i][0], acc[i][1], acc[i][2], acc[i][3]);
        *(float4*)&out[(size_t)(m0 + ty * 4 + i) * HH + tx * 4] = v;
    }
}

// ---------------------------------------------------------------------------
// Kernel 2: causal flash attention, fp32.
// grid = (TT/64, BB), block = 256. 64-query tile, online softmax.
// Smem: Qst/Kst (dim-major, pad 65), Vs (key-major, pad 65), Ss (pad 65),
// plus row stats. 67.3 KB dynamic.
// ---------------------------------------------------------------------------
#define ATTN_SMEM_FLOATS (4 * 64 * 65 + 3 * 64)
#define ATTN_SMEM_BYTES  (ATTN_SMEM_FLOATS * 4)

__global__ __launch_bounds__(256) void attn_kernel(float* __restrict__ out)
{
    extern __shared__ float sm[];
    float (*Qst)[65] = (float(*)[65])(sm);                 // [dim][query]
    float (*Kst)[65] = (float(*)[65])(sm + 64 * 65);       // [dim][key]
    float (*Vs )[65] = (float(*)[65])(sm + 2 * 64 * 65);   // [key][dim]
    float (*Ss )[65] = (float(*)[65])(sm + 3 * 64 * 65);   // [query][key]
    float* ms     = sm + 4 * 64 * 65;
    float* ls     = ms + 64;
    float* alphas = ls + 64;

    // Heaviest tiles launch first (causal imbalance)
    const int qt  = (int)gridDim.x - 1 - (int)blockIdx.x;
    const int b   = blockIdx.y;
    const int tid = threadIdx.x;
    const int tx  = tid & 15;
    const int ty  = tid >> 4;
    const int q0  = qt * 64;
    const size_t qbase = ((size_t)b * TT + q0) * HH;

    // Load Q tile, transposed to [dim][query]; pad-65 rows -> conflict-free store
    for (int idx = tid; idx < 64 * 64; idx += 256) {
        int q = idx >> 6;
        int h = idx & 63;
        Qst[h][q] = g_q[qbase + (size_t)q * HH + h];
    }
    if (tid < 64) { ms[tid] = -1e30f; ls[tid] = 0.0f; }

    float o[4][4] = {};
    __syncthreads();

    for (int kt = 0; kt <= qt; kt++) {
        const size_t kbase = ((size_t)b * TT + (size_t)kt * 64) * HH;
        // Load K (transposed) and V tiles
        for (int idx = tid; idx < 64 * 64; idx += 256) {
            int j = idx >> 6;
            int h = idx & 63;
            Kst[h][j] = g_k[kbase + (size_t)j * HH + h];
            Vs[j][h]  = g_v[kbase + (size_t)j * HH + h];
        }
        __syncthreads();

        // S = Q K^T  (4x4 per thread)
        float s[4][4] = {};
        #pragma unroll 16
        for (int k = 0; k < 64; k++) {
            float a0 = Qst[k][ty * 4 + 0];
            float a1 = Qst[k][ty * 4 + 1];
            float a2 = Qst[k][ty * 4 + 2];
            float a3 = Qst[k][ty * 4 + 3];
            float b0 = Kst[k][tx * 4 + 0];
            float b1 = Kst[k][tx * 4 + 1];
            float b2 = Kst[k][tx * 4 + 2];
            float b3 = Kst[k][tx * 4 + 3];
            s[0][0] += a0 * b0; s[0][1] += a0 * b1; s[0][2] += a0 * b2; s[0][3] += a0 * b3;
            s[1][0] += a1 * b0; s[1][1] += a1 * b1; s[1][2] += a1 * b2; s[1][3] += a1 * b3;
            s[2][0] += a2 * b0; s[2][1] += a2 * b1; s[2][2] += a2 * b2; s[2][3] += a2 * b3;
            s[3][0] += a3 * b0; s[3][1] += a3 * b1; s[3][2] += a3 * b2; s[3][3] += a3 * b3;
        }

        // scale + causal mask (diagonal tile only) + store to smem
        const bool diag = (kt == qt);
        #pragma unroll
        for (int i = 0; i < 4; i++) {
            #pragma unroll
            for (int j = 0; j < 4; j++) {
                float val = s[i][j] * 0.125f;   // 1/sqrt(64)
                if (diag && (tx * 4 + j) > (ty * 4 + i)) val = -1e30f;
                Ss[ty * 4 + i][tx * 4 + j] = val;
            }
        }
        __syncthreads();

        // Online softmax: one thread per query row
        if (tid < 64) {
            const int r = tid;
            float mx = -1e30f;
            #pragma unroll 8
            for (int j = 0; j < 64; j++) mx = fmaxf(mx, Ss[r][j]);
            const float newm = fmaxf(ms[r], mx);
            const float al   = __expf(ms[r] - newm);
            float sum = 0.0f;
            #pragma unroll 8
            for (int j = 0; j < 64; j++) {
                float p = __expf(Ss[r][j] - newm);
                Ss[r][j] = p;
                sum += p;
            }
            ls[r]     = ls[r] * al + sum;
            ms[r]     = newm;
            alphas[r] = al;
        }
        __syncthreads();

        // Rescale O, then O += P @ V
        #pragma unroll
        for (int i = 0; i < 4; i++) {
            const float al = alphas[ty * 4 + i];
            #pragma unroll
            for (int j = 0; j < 4; j++) o[i][j] *= al;
        }
        #pragma unroll 16
        for (int s2 = 0; s2 < 64; s2++) {
            float p0 = Ss[ty * 4 + 0][s2];
            float p1 = Ss[ty * 4 + 1][s2];
            float p2 = Ss[ty * 4 + 2][s2];
            float p3 = Ss[ty * 4 + 3][s2];
            float v0 = Vs[s2][tx * 4 + 0];
            float v1 = Vs[s2][tx * 4 + 1];
            float v2 = Vs[s2][tx * 4 + 2];
            float v3 = Vs[s2][tx * 4 + 3];
            o[0][0] += p0 * v0; o[0][1] += p0 * v1; o[0][2] += p0 * v2; o[0][3] += p0 * v3;
            o[1][0] += p1 * v0; o[1][1] += p1 * v1; o[1][2] += p1 * v2; o[1][3] += p1 * v3;
            o[2][0] += p2 * v0; o[2][1] += p2 * v1; o[2][2] += p2 * v2; o[2][3] += p2 * v3;
            o[3][0] += p3 * v0; o[3][1] += p3 * v1; o[3][2] += p3 * v2; o[3][3] += p3 * v3;
        }
        __syncthreads();
    }

    // Finalize: divide by l, write out
    #pragma unroll
    for (int i = 0; i < 4; i++) {
        const float inv = 1.0f / ls[ty * 4 + i];
        float4 v = make_float4(o[i][0] * inv, o[i][1] * inv, o[i][2] * inv, o[i][3] * inv);
        *(float4*)&out[qbase + (size_t)(ty * 4 + i) * HH + tx * 4] = v;
    }
}

// ---------------------------------------------------------------------------
extern "C" void kernel_launch(void* const* d_in, const int* in_sizes, int n_in,
                              void* d_out, int out_size)
{
    const float* x  = (const float*)d_in[0];
    const float* Wq = (const float*)d_in[1];
    const float* Wk = (const float*)d_in[2];
    const float* Wv = (const float*)d_in[3];
    float* out = (float*)d_out;

    (void)in_sizes; (void)n_in; (void)out_size;

    // Idempotent, capture-safe (not a stream op)
    cudaFuncSetAttribute(attn_kernel,
                         cudaFuncAttributeMaxDynamicSharedMemorySize,
                         ATTN_SMEM_BYTES);

    dim3 pgrid(MM / 64, 3);
    proj_kernel<<<pgrid, 256>>>(x, Wq, Wk, Wv);

    dim3 agrid(TT / 64, BB);
    attn_kernel<<<agrid, 256, ATTN_SMEM_BYTES>>>(out);
}

// round 7
// speedup vs baseline: 1.8611x; 1.8611x over previous
#include <cuda_runtime.h>
#include <cuda_bf16.h>
#include <cstdint>

// Problem constants
#define BB 8
#define TT 2048
#define CC 1024
#define HH 64
#define MM (BB * TT)   // 16384 rows

// Single dynamic-smem symbol shared by all kernels
extern __shared__ char dyn_smem[];

// ---------------------------------------------------------------------------
// Static device scratch (allocation-free)
// ---------------------------------------------------------------------------
__device__ float g_q[MM * HH];
__device__ float g_k[MM * HH];
__device__ float g_v[MM * HH];
__device__ __nv_bfloat16 g_xhi[MM * CC];
__device__ __nv_bfloat16 g_xlo[MM * CC];
__device__ __nv_bfloat16 g_wthi[3][HH * CC];   // W transposed: [n][k]
__device__ __nv_bfloat16 g_wtlo[3][HH * CC];
__device__ float g_os[2][MM * HH];             // split-K partial O (unnormalized)
__device__ float g_mstat[2][MM];
__device__ float g_lstat[2][MM];

// ---------------------------------------------------------------------------
// mma.sync bf16 (baseline PTX — legal on compute_103, no 'a' features)
// D(16x8,f32) += A(16x16,bf16 row) * B(16x8,bf16 col)
// ---------------------------------------------------------------------------
__device__ __forceinline__ void mma_bf16(float* c, const uint32_t* a, const uint32_t* b)
{
    asm volatile(
        "mma.sync.aligned.m16n8k16.row.col.f32.bf16.bf16.f32 "
        "{%0,%1,%2,%3}, {%4,%5,%6,%7}, {%8,%9}, {%0,%1,%2,%3};"
        : "+f"(c[0]), "+f"(c[1]), "+f"(c[2]), "+f"(c[3])
        : "r"(a[0]), "r"(a[1]), "r"(a[2]), "r"(a[3]), "r"(b[0]), "r"(b[1]));
}

// ---------------------------------------------------------------------------
// Kernel: convert x -> bf16 hi/lo.  grid = MM*CC/4/256 = 16384, block 256.
// ---------------------------------------------------------------------------
__global__ __launch_bounds__(256) void convert_x_kernel(const float* __restrict__ x)
{
    int i = blockIdx.x * 256 + threadIdx.x;           // float4 index
    float4 v = ((const float4*)x)[i];
    float f[4] = {v.x, v.y, v.z, v.w};
    __nv_bfloat16 h[4], l[4];
    #pragma unroll
    for (int j = 0; j < 4; j++) {
        h[j] = __float2bfloat16(f[j]);
        l[j] = __float2bfloat16(f[j] - __bfloat162float(h[j]));
    }
    __nv_bfloat162* dh = (__nv_bfloat162*)&g_xhi[(size_t)i * 4];
    __nv_bfloat162* dl = (__nv_bfloat162*)&g_xlo[(size_t)i * 4];
    dh[0] = __nv_bfloat162{h[0], h[1]}; dh[1] = __nv_bfloat162{h[2], h[3]};
    dl[0] = __nv_bfloat162{l[0], l[1]}; dl[1] = __nv_bfloat162{l[2], l[3]};
}

// Convert + transpose W -> [n][k] bf16 hi/lo. grid = 3*CC*HH/256 = 768.
__global__ __launch_bounds__(256) void convert_w_kernel(
    const float* __restrict__ Wq, const float* __restrict__ Wk, const float* __restrict__ Wv)
{
    int idx = blockIdx.x * 256 + threadIdx.x;
    int mat = idx / (CC * HH);
    int rem = idx - mat * (CC * HH);
    int k = rem >> 6;           // / HH
    int n = rem & 63;
    const float* W = (mat == 0) ? Wq : (mat == 1) ? Wk : Wv;
    float f = W[rem];
    __nv_bfloat16 h = __float2bfloat16(f);
    __nv_bfloat16 l = __float2bfloat16(f - __bfloat162float(h));
    g_wthi[mat][n * CC + k] = h;
    g_wtlo[mat][n * CC + k] = l;
}

// ---------------------------------------------------------------------------
// Kernel: QKV projection via mma.sync bf16 hi/lo split (3 accumulating passes).
// grid = (MM/128, 3), block = 256 (8 warps, 4x2 warp grid, 32x32 warp tiles).
// BM=128, BN=64, BK=64. Smem: Ahi/Alo [128][72] halves, Bhi/Blo [64][72].
// ---------------------------------------------------------------------------
#define ASTR 72   // smem row stride in halves (64 data + 8 pad) -> conflict-free quads

#define PROJ_SMEM_BYTES ((2 * 128 * ASTR + 2 * 64 * ASTR) * 2)   // 55296 B

__global__ __launch_bounds__(256) void proj_mma_kernel()
{
    uint16_t* sm16 = (uint16_t*)dyn_smem;
    uint16_t* Ahi = sm16;
    uint16_t* Alo = Ahi + 128 * ASTR;
    uint16_t* Bhi = Alo + 128 * ASTR;
    uint16_t* Blo = Bhi + 64 * ASTR;

    const int tid = threadIdx.x;
    const int wid = tid >> 5;
    const int lid = tid & 31;
    const int g   = lid >> 2;   // group-of-4 id (row within 8x8 tile)
    const int t   = lid & 3;    // thread-in-group

    const int mw = (wid >> 1) * 32;   // warp m offset within block tile
    const int nw = (wid & 1) * 32;    // warp n offset

    const int mat = blockIdx.y;
    const int m0  = blockIdx.x * 128;

    const __nv_bfloat16* wth = g_wthi[mat];
    const __nv_bfloat16* wtl = g_wtlo[mat];
    float* out = (mat == 0) ? g_q : (mat == 1) ? g_k : g_v;

    float c[2][4][4] = {};   // [mb][nb][reg]

    for (int k0 = 0; k0 < CC; k0 += 64) {
        // ---- load A tiles (128x64 halves each) : 1024 uint4 -> 4 per thread
        #pragma unroll
        for (int i = 0; i < 4; i++) {
            int idx = tid + i * 256;
            int r = idx >> 3, c8 = idx & 7;
            size_t gaddr = (size_t)(m0 + r) * CC + k0 + c8 * 8;
            *(uint4*)(Ahi + r * ASTR + c8 * 8) = *(const uint4*)&g_xhi[gaddr];
            *(uint4*)(Alo + r * ASTR + c8 * 8) = *(const uint4*)&g_xlo[gaddr];
        }
        // ---- load B tiles (64x64 halves each, [n][k]) : 512 uint4 -> 2 per thread
        #pragma unroll
        for (int i = 0; i < 2; i++) {
            int idx = tid + i * 256;
            int r = idx >> 3, c8 = idx & 7;
            size_t gaddr = (size_t)r * CC + k0 + c8 * 8;
            *(uint4*)(Bhi + r * ASTR + c8 * 8) = *(const uint4*)&wth[gaddr];
            *(uint4*)(Blo + r * ASTR + c8 * 8) = *(const uint4*)&wtl[gaddr];
        }
        __syncthreads();

        #pragma unroll
        for (int ks = 0; ks < 4; ks++) {
            const int kk = ks * 16;
            uint32_t ah[2][4], al[2][4], bh[4][2], bl[4][2];
            // A fragments: rows mw+mb*16+{g,g+8}, k pairs {2t, 2t+8}
            #pragma unroll
            for (int mb = 0; mb < 2; mb++) {
                const uint16_t* A0h = Ahi + (mw + mb * 16) * ASTR + kk;
                const uint16_t* A0l = Alo + (mw + mb * 16) * ASTR + kk;
                ah[mb][0] = *(const uint32_t*)(A0h + g * ASTR + 2 * t);
                ah[mb][1] = *(const uint32_t*)(A0h + (g + 8) * ASTR + 2 * t);
                ah[mb][2] = *(const uint32_t*)(A0h + g * ASTR + 2 * t + 8);
                ah[mb][3] = *(const uint32_t*)(A0h + (g + 8) * ASTR + 2 * t + 8);
                al[mb][0] = *(const uint32_t*)(A0l + g * ASTR + 2 * t);
                al[mb][1] = *(const uint32_t*)(A0l + (g + 8) * ASTR + 2 * t);
                al[mb][2] = *(const uint32_t*)(A0l + g * ASTR + 2 * t + 8);
                al[mb][3] = *(const uint32_t*)(A0l + (g + 8) * ASTR + 2 * t + 8);
            }
            // B fragments: n = nw+nb*8+g, k pairs {2t, 2t+8} (contiguous in [n][k])
            #pragma unroll
            for (int nb = 0; nb < 4; nb++) {
                const uint16_t* B0h = Bhi + (nw + nb * 8 + g) * ASTR + kk;
                const uint16_t* B0l = Blo + (nw + nb * 8 + g) * ASTR + kk;
                bh[nb][0] = *(const uint32_t*)(B0h + 2 * t);
                bh[nb][1] = *(const uint32_t*)(B0h + 2 * t + 8);
                bl[nb][0] = *(const uint32_t*)(B0l + 2 * t);
                bl[nb][1] = *(const uint32_t*)(B0l + 2 * t + 8);
            }
            #pragma unroll
            for (int mb = 0; mb < 2; mb++)
                #pragma unroll
                for (int nb = 0; nb < 4; nb++) {
                    mma_bf16(c[mb][nb], ah[mb], bh[nb]);   // hi*hi
                    mma_bf16(c[mb][nb], ah[mb], bl[nb]);   // hi*lo
                    mma_bf16(c[mb][nb], al[mb], bh[nb]);   // lo*hi
                }
        }
        __syncthreads();
    }

    // Epilogue: c0,c1 -> (row g, cols 2t,2t+1); c2,c3 -> (row g+8)
    #pragma unroll
    for (int mb = 0; mb < 2; mb++) {
        const int mrow = m0 + mw + mb * 16;
        #pragma unroll
        for (int nb = 0; nb < 4; nb++) {
            const int ncol = nw + nb * 8 + 2 * t;
            *(float2*)&out[(size_t)(mrow + g) * HH + ncol] =
                make_float2(c[mb][nb][0], c[mb][nb][1]);
            *(float2*)&out[(size_t)(mrow + g + 8) * HH + ncol] =
                make_float2(c[mb][nb][2], c[mb][nb][3]);
        }
    }
}

// ---------------------------------------------------------------------------
// Kernel: causal flash attention, fp32, split-K=2, register softmax.
// grid = (32, 8, 2), block = 256. 64q x 64k tiles, 4x4 per thread.
// ---------------------------------------------------------------------------
#define ATTN_SMEM_FLOATS (2 * 64 * 65 + 2 * 64 * 68)
#define ATTN_SMEM_BYTES  (ATTN_SMEM_FLOATS * 4)

__global__ __launch_bounds__(256) void attn_kernel()
{
    float* sm = (float*)dyn_smem;
    float (*Qst)[65] = (float(*)[65])(sm);                      // [dim][query]
    float (*Kst)[65] = (float(*)[65])(sm + 64 * 65);            // [dim][key]
    float (*Vs )[68] = (float(*)[68])(sm + 2 * 64 * 65);        // [key][dim] pad 68
    float (*Ss )[68] = (float(*)[68])(sm + 2 * 64 * 65 + 64*68);// [query][key] pad 68

    const int qt    = (int)gridDim.x - 1 - (int)blockIdx.x;     // heavy-first
    const int b     = blockIdx.y;
    const int split = blockIdx.z;
    const int tid = threadIdx.x;
    const int tx  = tid & 15;
    const int ty  = tid >> 4;
    const int q0  = qt * 64;
    const int rowbase = b * TT + q0;
    const size_t qbase = (size_t)rowbase * HH;

    const int nk   = qt + 1;
    const int half = (nk + 1) >> 1;
    const int klo  = split ? half : 0;
    const int khi  = split ? nk   : half;

    float* Oout = g_os[split];

    if (klo >= khi) {
        // empty split (qt==0, split==1): O=0, m=-inf, l=0
        #pragma unroll
        for (int i = 0; i < 4; i++)
            *(float4*)&Oout[qbase + (size_t)(ty * 4 + i) * HH + tx * 4] =
                make_float4(0.f, 0.f, 0.f, 0.f);
        if (tid < 64) {
            g_mstat[split][rowbase + tid] = -1e30f;
            g_lstat[split][rowbase + tid] = 0.0f;
        }
        return;
    }

    // Load Q tile transposed [dim][query]
    for (int idx = tid; idx < 64 * 64; idx += 256) {
        int q = idx >> 6, h = idx & 63;
        Qst[h][q] = g_q[qbase + (size_t)q * HH + h];
    }

    float o[4][4] = {};
    float m[4] = {-1e30f, -1e30f, -1e30f, -1e30f};
    float l[4] = {};

    for (int kt = klo; kt < khi; kt++) {
        __syncthreads();   // prev PV done before KV overwrite (also covers Q load, iter 1)
        const size_t kbase = ((size_t)b * TT + (size_t)kt * 64) * HH;
        for (int idx = tid; idx < 64 * 64; idx += 256) {
            int j = idx >> 6, h = idx & 63;
            Kst[h][j] = g_k[kbase + (size_t)j * HH + h];
            Vs[j][h]  = g_v[kbase + (size_t)j * HH + h];
        }
        __syncthreads();

        // S = Q K^T
        float s[4][4] = {};
        #pragma unroll 8
        for (int k = 0; k < 64; k++) {
            float a0 = Qst[k][ty * 4 + 0];
            float a1 = Qst[k][ty * 4 + 1];
            float a2 = Qst[k][ty * 4 + 2];
            float a3 = Qst[k][ty * 4 + 3];
            float b0 = Kst[k][tx * 4 + 0];
            float b1 = Kst[k][tx * 4 + 1];
            float b2 = Kst[k][tx * 4 + 2];
            float b3 = Kst[k][tx * 4 + 3];
            s[0][0] += a0 * b0; s[0][1] += a0 * b1; s[0][2] += a0 * b2; s[0][3] += a0 * b3;
            s[1][0] += a1 * b0; s[1][1] += a1 * b1; s[1][2] += a1 * b2; s[1][3] += a1 * b3;
            s[2][0] += a2 * b0; s[2][1] += a2 * b1; s[2][2] += a2 * b2; s[2][3] += a2 * b3;
            s[3][0] += a3 * b0; s[3][1] += a3 * b1; s[3][2] += a3 * b2; s[3][3] += a3 * b3;
        }

        // scale + causal mask (diag tile only)
        const bool diag = (kt == qt);
        #pragma unroll
        for (int i = 0; i < 4; i++)
            #pragma unroll
            for (int j = 0; j < 4; j++) {
                float val = s[i][j] * 0.125f;
                if (diag && (tx * 4 + j) > (ty * 4 + i)) val = -1e30f;
                s[i][j] = val;
            }

        // Register softmax: row reductions over the 16-lane tx group
        #pragma unroll
        for (int i = 0; i < 4; i++) {
            float rmax = fmaxf(fmaxf(s[i][0], s[i][1]), fmaxf(s[i][2], s[i][3]));
            rmax = fmaxf(rmax, __shfl_xor_sync(0xffffffffu, rmax, 8));
            rmax = fmaxf(rmax, __shfl_xor_sync(0xffffffffu, rmax, 4));
            rmax = fmaxf(rmax, __shfl_xor_sync(0xffffffffu, rmax, 2));
            rmax = fmaxf(rmax, __shfl_xor_sync(0xffffffffu, rmax, 1));
            const float newm = fmaxf(m[i], rmax);
            const float al   = __expf(m[i] - newm);
            float rsum = 0.0f;
            #pragma unroll
            for (int j = 0; j < 4; j++) {
                s[i][j] = __expf(s[i][j] - newm);
                rsum += s[i][j];
            }
            rsum += __shfl_xor_sync(0xffffffffu, rsum, 8);
            rsum += __shfl_xor_sync(0xffffffffu, rsum, 4);
            rsum += __shfl_xor_sync(0xffffffffu, rsum, 2);
            rsum += __shfl_xor_sync(0xffffffffu, rsum, 1);
            l[i] = l[i] * al + rsum;
            m[i] = newm;
            o[i][0] *= al; o[i][1] *= al; o[i][2] *= al; o[i][3] *= al;
            *(float4*)&Ss[ty * 4 + i][tx * 4] = make_float4(s[i][0], s[i][1], s[i][2], s[i][3]);
        }
        __syncthreads();

        // O += P @ V
        #pragma unroll 8
        for (int s2 = 0; s2 < 64; s2++) {
            float p0 = Ss[ty * 4 + 0][s2];
            float p1 = Ss[ty * 4 + 1][s2];
            float p2 = Ss[ty * 4 + 2][s2];
            float p3 = Ss[ty * 4 + 3][s2];
            float4 v = *(const float4*)&Vs[s2][tx * 4];
            o[0][0] += p0 * v.x; o[0][1] += p0 * v.y; o[0][2] += p0 * v.z; o[0][3] += p0 * v.w;
            o[1][0] += p1 * v.x; o[1][1] += p1 * v.y; o[1][2] += p1 * v.z; o[1][3] += p1 * v.w;
            o[2][0] += p2 * v.x; o[2][1] += p2 * v.y; o[2][2] += p2 * v.z; o[2][3] += p2 * v.w;
            o[3][0] += p3 * v.x; o[3][1] += p3 * v.y; o[3][2] += p3 * v.z; o[3][3] += p3 * v.w;
        }
    }

    // Write unnormalized O + stats
    #pragma unroll
    for (int i = 0; i < 4; i++) {
        const int row = ty * 4 + i;
        if (tx == 0) {
            g_mstat[split][rowbase + row] = m[i];
            g_lstat[split][rowbase + row] = l[i];
        }
        *(float4*)&Oout[qbase + (size_t)row * HH + tx * 4] =
            make_float4(o[i][0], o[i][1], o[i][2], o[i][3]);
    }
}

// ---------------------------------------------------------------------------
// Kernel: merge the two splits.  grid = MM*HH/4/256 = 1024, block 256.
// ---------------------------------------------------------------------------
__global__ __launch_bounds__(256) void merge_kernel(float* __restrict__ out)
{
    int gid = blockIdx.x * 256 + threadIdx.x;     // float4 index
    int row = gid >> 4;                           // (gid*4)/64
    float m0 = g_mstat[0][row], m1 = g_mstat[1][row];
    float l0 = g_lstat[0][row], l1 = g_lstat[1][row];
    float M  = fmaxf(m0, m1);
    float w0 = __expf(m0 - M);
    float w1 = __expf(m1 - M);
    float inv = 1.0f / (w0 * l0 + w1 * l1);
    float4 a = ((const float4*)g_os[0])[gid];
    float4 b = ((const float4*)g_os[1])[gid];
    float4 r;
    r.x = (w0 * a.x + w1 * b.x) * inv;
    r.y = (w0 * a.y + w1 * b.y) * inv;
    r.z = (w0 * a.z + w1 * b.z) * inv;
    r.w = (w0 * a.w + w1 * b.w) * inv;
    ((float4*)out)[gid] = r;
}

// ---------------------------------------------------------------------------
extern "C" void kernel_launch(void* const* d_in, const int* in_sizes, int n_in,
                              void* d_out, int out_size)
{
    const float* x  = (const float*)d_in[0];
    const float* Wq = (const float*)d_in[1];
    const float* Wk = (const float*)d_in[2];
    const float* Wv = (const float*)d_in[3];
    float* out = (float*)d_out;
    (void)in_sizes; (void)n_in; (void)out_size;

    cudaFuncSetAttribute(proj_mma_kernel, cudaFuncAttributeMaxDynamicSharedMemorySize,
                         PROJ_SMEM_BYTES);
    cudaFuncSetAttribute(attn_kernel, cudaFuncAttributeMaxDynamicSharedMemorySize,
                         ATTN_SMEM_BYTES);

    convert_x_kernel<<<MM * CC / 4 / 256, 256>>>(x);
    convert_w_kernel<<<3 * CC * HH / 256, 256>>>(Wq, Wk, Wv);

    dim3 ggrid(MM / 128, 3);
    proj_mma_kernel<<<ggrid, 256, PROJ_SMEM_BYTES>>>();

    dim3 agrid(TT / 64, BB, 2);
    attn_kernel<<<agrid, 256, ATTN_SMEM_BYTES>>>();

    merge_kernel<<<MM * HH / 4 / 256, 256>>>(out);
}

// round 8
// speedup vs baseline: 2.8708x; 1.5425x over previous
#include <cuda_runtime.h>
#include <cuda_bf16.h>
#include <cstdint>

// Problem constants
#define BB 8
#define TT 2048
#define CC 1024
#define HH 64
#define MM (BB * TT)   // 16384 rows

// Single dynamic-smem symbol shared by all kernels
extern __shared__ char dyn_smem[];

// ---------------------------------------------------------------------------
// Static device scratch (allocation-free)
// ---------------------------------------------------------------------------
__device__ __nv_bfloat16 g_xhi[MM * CC];
__device__ __nv_bfloat16 g_xlo[MM * CC];
__device__ __nv_bfloat16 g_wthi[3][HH * CC];   // W transposed: [n][k]
__device__ __nv_bfloat16 g_wtlo[3][HH * CC];
// Q/K bf16 hi/lo, row-major [m][64]
__device__ __nv_bfloat16 g_qhi[MM * HH];
__device__ __nv_bfloat16 g_qlo[MM * HH];
__device__ __nv_bfloat16 g_khi[MM * HH];
__device__ __nv_bfloat16 g_klo[MM * HH];
// V bf16 hi/lo, TRANSPOSED [dim][m]
__device__ __nv_bfloat16 g_vthi[HH * MM];
__device__ __nv_bfloat16 g_vtlo[HH * MM];
// split-K partials
__device__ float g_os[2][MM * HH];
__device__ float g_mstat[2][MM];
__device__ float g_lstat[2][MM];

// ---------------------------------------------------------------------------
// mma.sync bf16 (baseline PTX — legal on compute_103)
// D(16x8,f32) += A(16x16,bf16 row) * B(16x8,bf16 col)
// ---------------------------------------------------------------------------
__device__ __forceinline__ void mma_bf16(float* c, const uint32_t* a, const uint32_t* b)
{
    asm volatile(
        "mma.sync.aligned.m16n8k16.row.col.f32.bf16.bf16.f32 "
        "{%0,%1,%2,%3}, {%4,%5,%6,%7}, {%8,%9}, {%0,%1,%2,%3};"
        : "+f"(c[0]), "+f"(c[1]), "+f"(c[2]), "+f"(c[3])
        : "r"(a[0]), "r"(a[1]), "r"(a[2]), "r"(a[3]), "r"(b[0]), "r"(b[1]));
}

__device__ __forceinline__ uint32_t packbf(float a, float b)
{
    __nv_bfloat162 t;
    t.x = __float2bfloat16(a);
    t.y = __float2bfloat16(b);
    return *(uint32_t*)&t;
}

// ---------------------------------------------------------------------------
// Kernel: convert x -> bf16 hi/lo.  grid = MM*CC/4/256 = 16384, block 256.
// ---------------------------------------------------------------------------
__global__ __launch_bounds__(256) void convert_x_kernel(const float* __restrict__ x)
{
    int i = blockIdx.x * 256 + threadIdx.x;           // float4 index
    float4 v = ((const float4*)x)[i];
    float f[4] = {v.x, v.y, v.z, v.w};
    __nv_bfloat16 h[4], l[4];
    #pragma unroll
    for (int j = 0; j < 4; j++) {
        h[j] = __float2bfloat16(f[j]);
        l[j] = __float2bfloat16(f[j] - __bfloat162float(h[j]));
    }
    __nv_bfloat162* dh = (__nv_bfloat162*)&g_xhi[(size_t)i * 4];
    __nv_bfloat162* dl = (__nv_bfloat162*)&g_xlo[(size_t)i * 4];
    dh[0] = __nv_bfloat162{h[0], h[1]}; dh[1] = __nv_bfloat162{h[2], h[3]};
    dl[0] = __nv_bfloat162{l[0], l[1]}; dl[1] = __nv_bfloat162{l[2], l[3]};
}

// Convert + transpose W -> [n][k] bf16 hi/lo. grid = 3*CC*HH/256 = 768.
__global__ __launch_bounds__(256) void convert_w_kernel(
    const float* __restrict__ Wq, const float* __restrict__ Wk, const float* __restrict__ Wv)
{
    int idx = blockIdx.x * 256 + threadIdx.x;
    int mat = idx / (CC * HH);
    int rem = idx - mat * (CC * HH);
    int k = rem >> 6;           // / HH
    int n = rem & 63;
    const float* W = (mat == 0) ? Wq : (mat == 1) ? Wk : Wv;
    float f = W[rem];
    __nv_bfloat16 h = __float2bfloat16(f);
    __nv_bfloat16 l = __float2bfloat16(f - __bfloat162float(h));
    g_wthi[mat][n * CC + k] = h;
    g_wtlo[mat][n * CC + k] = l;
}

// ---------------------------------------------------------------------------
// Kernel: QKV projection via mma.sync bf16 hi/lo split (3 accumulating passes).
// grid = (MM/128, 3), block = 256 (8 warps, 4x2 warp grid, 32x32 warp tiles).
// Epilogue writes bf16 hi/lo directly (Q/K row-major, V transposed).
// ---------------------------------------------------------------------------
#define ASTR 72   // smem row stride in halves (64 data + 8 pad)

#define PROJ_SMEM_BYTES ((2 * 128 * ASTR + 2 * 64 * ASTR) * 2)   // 55296 B

__global__ __launch_bounds__(256) void proj_mma_kernel()
{
    uint16_t* sm16 = (uint16_t*)dyn_smem;
    uint16_t* Ahi = sm16;
    uint16_t* Alo = Ahi + 128 * ASTR;
    uint16_t* Bhi = Alo + 128 * ASTR;
    uint16_t* Blo = Bhi + 64 * ASTR;

    const int tid = threadIdx.x;
    const int wid = tid >> 5;
    const int lid = tid & 31;
    const int g   = lid >> 2;
    const int t   = lid & 3;

    const int mw = (wid >> 1) * 32;
    const int nw = (wid & 1) * 32;

    const int mat = blockIdx.y;
    const int m0  = blockIdx.x * 128;

    const __nv_bfloat16* wth = g_wthi[mat];
    const __nv_bfloat16* wtl = g_wtlo[mat];

    float c[2][4][4] = {};

    for (int k0 = 0; k0 < CC; k0 += 64) {
        #pragma unroll
        for (int i = 0; i < 4; i++) {
            int idx = tid + i * 256;
            int r = idx >> 3, c8 = idx & 7;
            size_t gaddr = (size_t)(m0 + r) * CC + k0 + c8 * 8;
            *(uint4*)(Ahi + r * ASTR + c8 * 8) = *(const uint4*)&g_xhi[gaddr];
            *(uint4*)(Alo + r * ASTR + c8 * 8) = *(const uint4*)&g_xlo[gaddr];
        }
        #pragma unroll
        for (int i = 0; i < 2; i++) {
            int idx = tid + i * 256;
            int r = idx >> 3, c8 = idx & 7;
            size_t gaddr = (size_t)r * CC + k0 + c8 * 8;
            *(uint4*)(Bhi + r * ASTR + c8 * 8) = *(const uint4*)&wth[gaddr];
            *(uint4*)(Blo + r * ASTR + c8 * 8) = *(const uint4*)&wtl[gaddr];
        }
        __syncthreads();

        #pragma unroll
        for (int ks = 0; ks < 4; ks++) {
            const int kk = ks * 16;
            uint32_t ah[2][4], al[2][4], bh[4][2], bl[4][2];
            #pragma unroll
            for (int mb = 0; mb < 2; mb++) {
                const uint16_t* A0h = Ahi + (mw + mb * 16) * ASTR + kk;
                const uint16_t* A0l = Alo + (mw + mb * 16) * ASTR + kk;
                ah[mb][0] = *(const uint32_t*)(A0h + g * ASTR + 2 * t);
                ah[mb][1] = *(const uint32_t*)(A0h + (g + 8) * ASTR + 2 * t);
                ah[mb][2] = *(const uint32_t*)(A0h + g * ASTR + 2 * t + 8);
                ah[mb][3] = *(const uint32_t*)(A0h + (g + 8) * ASTR + 2 * t + 8);
                al[mb][0] = *(const uint32_t*)(A0l + g * ASTR + 2 * t);
                al[mb][1] = *(const uint32_t*)(A0l + (g + 8) * ASTR + 2 * t);
                al[mb][2] = *(const uint32_t*)(A0l + g * ASTR + 2 * t + 8);
                al[mb][3] = *(const uint32_t*)(A0l + (g + 8) * ASTR + 2 * t + 8);
            }
            #pragma unroll
            for (int nb = 0; nb < 4; nb++) {
                const uint16_t* B0h = Bhi + (nw + nb * 8 + g) * ASTR + kk;
                const uint16_t* B0l = Blo + (nw + nb * 8 + g) * ASTR + kk;
                bh[nb][0] = *(const uint32_t*)(B0h + 2 * t);
                bh[nb][1] = *(const uint32_t*)(B0h + 2 * t + 8);
                bl[nb][0] = *(const uint32_t*)(B0l + 2 * t);
                bl[nb][1] = *(const uint32_t*)(B0l + 2 * t + 8);
            }
            #pragma unroll
            for (int mb = 0; mb < 2; mb++)
                #pragma unroll
                for (int nb = 0; nb < 4; nb++) {
                    mma_bf16(c[mb][nb], ah[mb], bh[nb]);
                    mma_bf16(c[mb][nb], ah[mb], bl[nb]);
                    mma_bf16(c[mb][nb], al[mb], bh[nb]);
                }
        }
        __syncthreads();
    }

    // Epilogue -> bf16 hi/lo
    #pragma unroll
    for (int mb = 0; mb < 2; mb++) {
        const int r0 = m0 + mw + mb * 16 + g;
        const int r1 = r0 + 8;
        #pragma unroll
        for (int nb = 0; nb < 4; nb++) {
            const int col = nw + nb * 8 + 2 * t;
            float v00 = c[mb][nb][0], v01 = c[mb][nb][1];
            float v10 = c[mb][nb][2], v11 = c[mb][nb][3];
            uint32_t h0 = packbf(v00, v01);
            uint32_t h1 = packbf(v10, v11);
            __nv_bfloat162 h0b = *(__nv_bfloat162*)&h0;
            __nv_bfloat162 h1b = *(__nv_bfloat162*)&h1;
            uint32_t l0 = packbf(v00 - __bfloat162float(h0b.x), v01 - __bfloat162float(h0b.y));
            uint32_t l1 = packbf(v10 - __bfloat162float(h1b.x), v11 - __bfloat162float(h1b.y));
            if (mat == 0) {
                *(uint32_t*)&g_qhi[(size_t)r0 * HH + col] = h0;
                *(uint32_t*)&g_qlo[(size_t)r0 * HH + col] = l0;
                *(uint32_t*)&g_qhi[(size_t)r1 * HH + col] = h1;
                *(uint32_t*)&g_qlo[(size_t)r1 * HH + col] = l1;
            } else if (mat == 1) {
                *(uint32_t*)&g_khi[(size_t)r0 * HH + col] = h0;
                *(uint32_t*)&g_klo[(size_t)r0 * HH + col] = l0;
                *(uint32_t*)&g_khi[(size_t)r1 * HH + col] = h1;
                *(uint32_t*)&g_klo[(size_t)r1 * HH + col] = l1;
            } else {
                __nv_bfloat162 l0b = *(__nv_bfloat162*)&l0;
                __nv_bfloat162 l1b = *(__nv_bfloat162*)&l1;
                g_vthi[(size_t)col * MM + r0]       = h0b.x;
                g_vthi[(size_t)(col + 1) * MM + r0] = h0b.y;
                g_vthi[(size_t)col * MM + r1]       = h1b.x;
                g_vthi[(size_t)(col + 1) * MM + r1] = h1b.y;
                g_vtlo[(size_t)col * MM + r0]       = l0b.x;
                g_vtlo[(size_t)(col + 1) * MM + r0] = l0b.y;
                g_vtlo[(size_t)col * MM + r1]       = l1b.x;
                g_vtlo[(size_t)(col + 1) * MM + r1] = l1b.y;
            }
        }
    }
}

// ---------------------------------------------------------------------------
// Kernel: causal flash attention on mma.sync bf16 (hi/lo 3-pass), split-K=2.
// grid = (16, 8, 2), block = 256 (8 warps x m16 rows = 128 queries/CTA).
// Smem: Khi/Klo/Vthi/Vtlo [64][72] halves = 36864 B.
// ---------------------------------------------------------------------------
#define ATTN_SMEM_BYTES (4 * 64 * ASTR * 2)

__global__ __launch_bounds__(256) void attn_kernel()
{
    uint16_t* sm16 = (uint16_t*)dyn_smem;
    uint16_t* Khi  = sm16;
    uint16_t* Klo  = Khi + 64 * ASTR;
    uint16_t* Vthi = Klo + 64 * ASTR;
    uint16_t* Vtlo = Vthi + 64 * ASTR;

    const int qt    = 15 - (int)blockIdx.x;        // heavy-first
    const int b     = blockIdx.y;
    const int split = blockIdx.z;
    const int tid = threadIdx.x;
    const int w   = tid >> 5;
    const int lid = tid & 31;
    const int g   = lid >> 2;
    const int t   = lid & 3;

    const int q0      = qt * 128;
    const int rowbase = b * TT + q0;

    // key-tile range for this split
    const int nk  = 2 * qt + 2;
    const int klo_t = split ? (qt + 1) : 0;
    const int khi_t = split ? nk : (qt + 1);

    // ---- stage Q fragments into registers (two 64-row chunks via K buffers)
    uint32_t qh[4][4], ql[4][4];
    #pragma unroll
    for (int ch = 0; ch < 2; ch++) {
        #pragma unroll
        for (int i = 0; i < 2; i++) {
            int idx = tid + i * 256;
            int r = idx >> 3, c8 = idx & 7;
            size_t gaddr = (size_t)(rowbase + 64 * ch + r) * HH + c8 * 8;
            *(uint4*)(Khi + r * ASTR + c8 * 8) = *(const uint4*)&g_qhi[gaddr];
            *(uint4*)(Klo + r * ASTR + c8 * 8) = *(const uint4*)&g_qlo[gaddr];
        }
        __syncthreads();
        if ((w >> 2) == ch) {
            const int lr = (w & 3) * 16;
            #pragma unroll
            for (int ks = 0; ks < 4; ks++) {
                const uint16_t* Qh0 = Khi + (lr + g) * ASTR + ks * 16;
                const uint16_t* Ql0 = Klo + (lr + g) * ASTR + ks * 16;
                qh[ks][0] = *(const uint32_t*)(Qh0 + 2 * t);
                qh[ks][1] = *(const uint32_t*)(Qh0 + 8 * ASTR + 2 * t);
                qh[ks][2] = *(const uint32_t*)(Qh0 + 2 * t + 8);
                qh[ks][3] = *(const uint32_t*)(Qh0 + 8 * ASTR + 2 * t + 8);
                ql[ks][0] = *(const uint32_t*)(Ql0 + 2 * t);
                ql[ks][1] = *(const uint32_t*)(Ql0 + 8 * ASTR + 2 * t);
                ql[ks][2] = *(const uint32_t*)(Ql0 + 2 * t + 8);
                ql[ks][3] = *(const uint32_t*)(Ql0 + 8 * ASTR + 2 * t + 8);
            }
        }
        __syncthreads();
    }

    const int qrow0 = q0 + w * 16 + g;   // absolute query rows of this thread
    const int qrow1 = qrow0 + 8;

    float o[8][4] = {};
    float m0r = -1e30f, m1r = -1e30f;
    float l0r = 0.0f,   l1r = 0.0f;

    for (int kt = klo_t; kt < khi_t; kt++) {
        const int kb = kt * 64;
        __syncthreads();
        // load K tile [key][dim] and Vt tile [dim][key]
        #pragma unroll
        for (int i = 0; i < 2; i++) {
            int idx = tid + i * 256;
            int r = idx >> 3, c8 = idx & 7;
            size_t ka = (size_t)(b * TT + kb + r) * HH + c8 * 8;
            *(uint4*)(Khi + r * ASTR + c8 * 8) = *(const uint4*)&g_khi[ka];
            *(uint4*)(Klo + r * ASTR + c8 * 8) = *(const uint4*)&g_klo[ka];
            size_t va = (size_t)r * MM + b * TT + kb + c8 * 8;
            *(uint4*)(Vthi + r * ASTR + c8 * 8) = *(const uint4*)&g_vthi[va];
            *(uint4*)(Vtlo + r * ASTR + c8 * 8) = *(const uint4*)&g_vtlo[va];
        }
        __syncthreads();

        // ---- S = Q K^T (3-pass hi/lo)
        float s[8][4] = {};
        #pragma unroll
        for (int ks = 0; ks < 4; ks++) {
            #pragma unroll
            for (int nb = 0; nb < 8; nb++) {
                const uint16_t* K0h = Khi + (nb * 8 + g) * ASTR + ks * 16;
                const uint16_t* K0l = Klo + (nb * 8 + g) * ASTR + ks * 16;
                uint32_t kh[2], kl[2];
                kh[0] = *(const uint32_t*)(K0h + 2 * t);
                kh[1] = *(const uint32_t*)(K0h + 2 * t + 8);
                kl[0] = *(const uint32_t*)(K0l + 2 * t);
                kl[1] = *(const uint32_t*)(K0l + 2 * t + 8);
                mma_bf16(s[nb], qh[ks], kh);
                mma_bf16(s[nb], qh[ks], kl);
                mma_bf16(s[nb], ql[ks], kh);
            }
        }

        // ---- scale + causal mask (mask value -1e38 < running-max init -1e30)
        const bool maskTile = (kb + 63 > q0);
        #pragma unroll
        for (int nb = 0; nb < 8; nb++) {
            const int key0 = kb + nb * 8 + 2 * t;
            s[nb][0] *= 0.125f; s[nb][1] *= 0.125f;
            s[nb][2] *= 0.125f; s[nb][3] *= 0.125f;
            if (maskTile) {
                if (key0     > qrow0) s[nb][0] = -1e38f;
                if (key0 + 1 > qrow0) s[nb][1] = -1e38f;
                if (key0     > qrow1) s[nb][2] = -1e38f;
                if (key0 + 1 > qrow1) s[nb][3] = -1e38f;
            }
        }

        // ---- online softmax (rows g and g+8), reduce across 4-lane t-group
        float mx0 = -1e38f, mx1 = -1e38f;
        #pragma unroll
        for (int nb = 0; nb < 8; nb++) {
            mx0 = fmaxf(mx0, fmaxf(s[nb][0], s[nb][1]));
            mx1 = fmaxf(mx1, fmaxf(s[nb][2], s[nb][3]));
        }
        mx0 = fmaxf(mx0, __shfl_xor_sync(0xffffffffu, mx0, 1));
        mx0 = fmaxf(mx0, __shfl_xor_sync(0xffffffffu, mx0, 2));
        mx1 = fmaxf(mx1, __shfl_xor_sync(0xffffffffu, mx1, 1));
        mx1 = fmaxf(mx1, __shfl_xor_sync(0xffffffffu, mx1, 2));

        const float nm0 = fmaxf(m0r, mx0);
        const float nm1 = fmaxf(m1r, mx1);
        const float al0 = __expf(m0r - nm0);
        const float al1 = __expf(m1r - nm1);
        float sum0 = 0.0f, sum1 = 0.0f;
        #pragma unroll
        for (int nb = 0; nb < 8; nb++) {
            s[nb][0] = __expf(s[nb][0] - nm0);
            s[nb][1] = __expf(s[nb][1] - nm0);
            s[nb][2] = __expf(s[nb][2] - nm1);
            s[nb][3] = __expf(s[nb][3] - nm1);
            sum0 += s[nb][0] + s[nb][1];
            sum1 += s[nb][2] + s[nb][3];
        }
        sum0 += __shfl_xor_sync(0xffffffffu, sum0, 1);
        sum0 += __shfl_xor_sync(0xffffffffu, sum0, 2);
        sum1 += __shfl_xor_sync(0xffffffffu, sum1, 1);
        sum1 += __shfl_xor_sync(0xffffffffu, sum1, 2);
        l0r = l0r * al0 + sum0;  m0r = nm0;
        l1r = l1r * al1 + sum1;  m1r = nm1;
        #pragma unroll
        for (int nb = 0; nb < 8; nb++) {
            o[nb][0] *= al0; o[nb][1] *= al0;
            o[nb][2] *= al1; o[nb][3] *= al1;
        }

        // ---- O += P V (P from registers, 3-pass hi/lo)
        #pragma unroll
        for (int ks = 0; ks < 4; ks++) {
            float p00 = s[2 * ks][0],     p01 = s[2 * ks][1];
            float p02 = s[2 * ks][2],     p03 = s[2 * ks][3];
            float p10 = s[2 * ks + 1][0], p11 = s[2 * ks + 1][1];
            float p12 = s[2 * ks + 1][2], p13 = s[2 * ks + 1][3];
            uint32_t aPh[4], aPl[4];
            aPh[0] = packbf(p00, p01);
            aPh[1] = packbf(p02, p03);
            aPh[2] = packbf(p10, p11);
            aPh[3] = packbf(p12, p13);
            __nv_bfloat162 b0 = *(__nv_bfloat162*)&aPh[0];
            __nv_bfloat162 b1 = *(__nv_bfloat162*)&aPh[1];
            __nv_bfloat162 b2 = *(__nv_bfloat162*)&aPh[2];
            __nv_bfloat162 b3 = *(__nv_bfloat162*)&aPh[3];
            aPl[0] = packbf(p00 - __bfloat162float(b0.x), p01 - __bfloat162float(b0.y));
            aPl[1] = packbf(p02 - __bfloat162float(b1.x), p03 - __bfloat162float(b1.y));
            aPl[2] = packbf(p10 - __bfloat162float(b2.x), p11 - __bfloat162float(b2.y));
            aPl[3] = packbf(p12 - __bfloat162float(b3.x), p13 - __bfloat162float(b3.y));
            #pragma unroll
            for (int nb = 0; nb < 8; nb++) {
                const uint16_t* V0h = Vthi + (nb * 8 + g) * ASTR + ks * 16;
                const uint16_t* V0l = Vtlo + (nb * 8 + g) * ASTR + ks * 16;
                uint32_t vh[2], vl[2];
                vh[0] = *(const uint32_t*)(V0h + 2 * t);
                vh[1] = *(const uint32_t*)(V0h + 2 * t + 8);
                vl[0] = *(const uint32_t*)(V0l + 2 * t);
                vl[1] = *(const uint32_t*)(V0l + 2 * t + 8);
                mma_bf16(o[nb], aPh, vh);
                mma_bf16(o[nb], aPh, vl);
                mma_bf16(o[nb], aPl, vh);
            }
        }
    }

    // ---- write unnormalized O + stats (merge kernel normalizes)
    float* Oout = g_os[split];
    const size_t ob0 = (size_t)(rowbase + w * 16 + g) * HH;
    const size_t ob1 = (size_t)(rowbase + w * 16 + g + 8) * HH;
    #pragma unroll
    for (int nb = 0; nb < 8; nb++) {
        const int col = nb * 8 + 2 * t;
        *(float2*)&Oout[ob0 + col] = make_float2(o[nb][0], o[nb][1]);
        *(float2*)&Oout[ob1 + col] = make_float2(o[nb][2], o[nb][3]);
    }
    if (t == 0) {
        g_mstat[split][rowbase + w * 16 + g]     = m0r;
        g_lstat[split][rowbase + w * 16 + g]     = l0r;
        g_mstat[split][rowbase + w * 16 + g + 8] = m1r;
        g_lstat[split][rowbase + w * 16 + g + 8] = l1r;
    }
}

// ---------------------------------------------------------------------------
// Kernel: merge the two splits.  grid = MM*HH/4/256 = 1024, block 256.
// ---------------------------------------------------------------------------
__global__ __launch_bounds__(256) void merge_kernel(float* __restrict__ out)
{
    int gid = blockIdx.x * 256 + threadIdx.x;     // float4 index
    int row = gid >> 4;
    float m0 = g_mstat[0][row], m1 = g_mstat[1][row];
    float l0 = g_lstat[0][row], l1 = g_lstat[1][row];
    float M  = fmaxf(m0, m1);
    float w0 = __expf(m0 - M);
    float w1 = __expf(m1 - M);
    float inv = 1.0f / (w0 * l0 + w1 * l1);
    float4 a = ((const float4*)g_os[0])[gid];
    float4 b = ((const float4*)g_os[1])[gid];
    float4 r;
    r.x = (w0 * a.x + w1 * b.x) * inv;
    r.y = (w0 * a.y + w1 * b.y) * inv;
    r.z = (w0 * a.z + w1 * b.z) * inv;
    r.w = (w0 * a.w + w1 * b.w) * inv;
    ((float4*)out)[gid] = r;
}

// ---------------------------------------------------------------------------
extern "C" void kernel_launch(void* const* d_in, const int* in_sizes, int n_in,
                              void* d_out, int out_size)
{
    const float* x  = (const float*)d_in[0];
    const float* Wq = (const float*)d_in[1];
    const float* Wk = (const float*)d_in[2];
    const float* Wv = (const float*)d_in[3];
    float* out = (float*)d_out;
    (void)in_sizes; (void)n_in; (void)out_size;

    cudaFuncSetAttribute(proj_mma_kernel, cudaFuncAttributeMaxDynamicSharedMemorySize,
                         PROJ_SMEM_BYTES);
    cudaFuncSetAttribute(attn_kernel, cudaFuncAttributeMaxDynamicSharedMemorySize,
                         ATTN_SMEM_BYTES);

    convert_x_kernel<<<MM * CC / 4 / 256, 256>>>(x);
    convert_w_kernel<<<3 * CC * HH / 256, 256>>>(Wq, Wk, Wv);

    dim3 ggrid(MM / 128, 3);
    proj_mma_kernel<<<ggrid, 256, PROJ_SMEM_BYTES>>>();

    dim3 agrid(16, BB, 2);
    attn_kernel<<<agrid, 256, ATTN_SMEM_BYTES>>>();

    merge_kernel<<<MM * HH / 4 / 256, 256>>>(out);
}

// round 9
// speedup vs baseline: 3.1834x; 1.1089x over previous
#include <cuda_runtime.h>
#include <cuda_bf16.h>
#include <cstdint>

// Problem constants
#define BB 8
#define TT 2048
#define CC 1024
#define HH 64
#define MM (BB * TT)   // 16384 rows

// Single dynamic-smem symbol shared by all kernels
extern __shared__ char dyn_smem[];

// ---------------------------------------------------------------------------
// Static device scratch (allocation-free)
// ---------------------------------------------------------------------------
__device__ __nv_bfloat16 g_wthi[3][HH * CC];   // W transposed: [n][k]
__device__ __nv_bfloat16 g_wtlo[3][HH * CC];
// Q/K bf16 hi/lo, row-major [m][64]
__device__ __nv_bfloat16 g_qhi[MM * HH];
__device__ __nv_bfloat16 g_qlo[MM * HH];
__device__ __nv_bfloat16 g_khi[MM * HH];
__device__ __nv_bfloat16 g_klo[MM * HH];
// V bf16 hi/lo, TRANSPOSED [dim][m]
__device__ __nv_bfloat16 g_vthi[HH * MM];
__device__ __nv_bfloat16 g_vtlo[HH * MM];
// split-K partials
__device__ float g_os[2][MM * HH];
__device__ float g_mstat[2][MM];
__device__ float g_lstat[2][MM];

// ---------------------------------------------------------------------------
// PTX helpers (all baseline PTX — legal on compute_103)
// ---------------------------------------------------------------------------
__device__ __forceinline__ uint32_t smem_u32(const void* p) {
    uint32_t a;
    asm("{ .reg .u64 t; cvta.to.shared.u64 t, %1; cvt.u32.u64 %0, t; }"
        : "=r"(a) : "l"(p));
    return a;
}

__device__ __forceinline__ void cp16(uint32_t s, const void* g) {
    asm volatile("cp.async.cg.shared.global [%0], [%1], 16;" :: "r"(s), "l"(g));
}
#define CP_COMMIT() asm volatile("cp.async.commit_group;")

// D(16x8,f32) += A(16x16,bf16 row) * B(16x8,bf16 col)
__device__ __forceinline__ void mma_bf16(float* c, const uint32_t* a, const uint32_t* b)
{
    asm volatile(
        "mma.sync.aligned.m16n8k16.row.col.f32.bf16.bf16.f32 "
        "{%0,%1,%2,%3}, {%4,%5,%6,%7}, {%8,%9}, {%0,%1,%2,%3};"
        : "+f"(c[0]), "+f"(c[1]), "+f"(c[2]), "+f"(c[3])
        : "r"(a[0]), "r"(a[1]), "r"(a[2]), "r"(a[3]), "r"(b[0]), "r"(b[1]));
}

__device__ __forceinline__ uint32_t packbf(float a, float b)
{
    __nv_bfloat162 t;
    t.x = __float2bfloat16(a);
    t.y = __float2bfloat16(b);
    return *(uint32_t*)&t;
}

// ---------------------------------------------------------------------------
// Convert + transpose W -> [n][k] bf16 hi/lo. grid = 3*CC*HH/256 = 768.
// ---------------------------------------------------------------------------
__global__ __launch_bounds__(256) void convert_w_kernel(
    const float* __restrict__ Wq, const float* __restrict__ Wk, const float* __restrict__ Wv)
{
    int idx = blockIdx.x * 256 + threadIdx.x;
    int mat = idx / (CC * HH);
    int rem = idx - mat * (CC * HH);
    int k = rem >> 6;
    int n = rem & 63;
    const float* W = (mat == 0) ? Wq : (mat == 1) ? Wk : Wv;
    float f = W[rem];
    __nv_bfloat16 h = __float2bfloat16(f);
    __nv_bfloat16 l = __float2bfloat16(f - __bfloat162float(h));
    g_wthi[mat][n * CC + k] = h;
    g_wtlo[mat][n * CC + k] = l;
}

// ---------------------------------------------------------------------------
// Kernel: QKV projection, fused fp32->bf16 hi/lo convert + register-prefetch
// pipeline + mma.sync 3-pass. grid = (MM/128, 3), block = 256.
// ---------------------------------------------------------------------------
#define ASTR 72   // smem row stride in halves (64 data + 8 pad)

#define PROJ_SMEM_BYTES ((2 * 128 * ASTR + 2 * 64 * ASTR) * 2)   // 55296 B

__global__ __launch_bounds__(256) void proj_mma_kernel(const float* __restrict__ x)
{
    uint16_t* sm16 = (uint16_t*)dyn_smem;
    uint16_t* Ahi = sm16;
    uint16_t* Alo = Ahi + 128 * ASTR;
    uint16_t* Bhi = Alo + 128 * ASTR;
    uint16_t* Blo = Bhi + 64 * ASTR;

    const int tid = threadIdx.x;
    const int wid = tid >> 5;
    const int lid = tid & 31;
    const int g   = lid >> 2;
    const int t   = lid & 3;

    const int mw = (wid >> 1) * 32;
    const int nw = (wid & 1) * 32;

    const int mat = blockIdx.y;
    const int m0  = blockIdx.x * 128;

    const __nv_bfloat16* wth = g_wthi[mat];
    const __nv_bfloat16* wtl = g_wtlo[mat];

    float c[2][4][4] = {};

    // prefetch registers
    float4 ax[8];
    uint4  brh[2], brl[2];

    // ---- prologue: load chunk 0
    #pragma unroll
    for (int i = 0; i < 8; i++) {
        int idx = tid + i * 256;
        int r = idx >> 4, c4 = idx & 15;
        ax[i] = *(const float4*)&x[(size_t)(m0 + r) * CC + c4 * 4];
    }
    #pragma unroll
    for (int i = 0; i < 2; i++) {
        int idx = tid + i * 256;
        int r = idx >> 3, c8 = idx & 7;
        brh[i] = *(const uint4*)&wth[(size_t)r * CC + c8 * 8];
        brl[i] = *(const uint4*)&wtl[(size_t)r * CC + c8 * 8];
    }

    for (int ch = 0; ch < 16; ch++) {
        // ---- store prefetched regs -> smem (convert A fp32 to hi/lo)
        #pragma unroll
        for (int i = 0; i < 8; i++) {
            int idx = tid + i * 256;
            int r = idx >> 4, c4 = idx & 15;
            float4 v = ax[i];
            uint32_t h0 = packbf(v.x, v.y);
            uint32_t h1 = packbf(v.z, v.w);
            __nv_bfloat162 hb0 = *(__nv_bfloat162*)&h0;
            __nv_bfloat162 hb1 = *(__nv_bfloat162*)&h1;
            uint32_t l0 = packbf(v.x - __bfloat162float(hb0.x), v.y - __bfloat162float(hb0.y));
            uint32_t l1 = packbf(v.z - __bfloat162float(hb1.x), v.w - __bfloat162float(hb1.y));
            *(uint2*)(Ahi + r * ASTR + c4 * 4) = make_uint2(h0, h1);
            *(uint2*)(Alo + r * ASTR + c4 * 4) = make_uint2(l0, l1);
        }
        #pragma unroll
        for (int i = 0; i < 2; i++) {
            int idx = tid + i * 256;
            int r = idx >> 3, c8 = idx & 7;
            *(uint4*)(Bhi + r * ASTR + c8 * 8) = brh[i];
            *(uint4*)(Blo + r * ASTR + c8 * 8) = brl[i];
        }
        __syncthreads();

        // ---- issue loads for next chunk (latency hidden under MMAs)
        if (ch < 15) {
            const int k0n = (ch + 1) * 64;
            #pragma unroll
            for (int i = 0; i < 8; i++) {
                int idx = tid + i * 256;
                int r = idx >> 4, c4 = idx & 15;
                ax[i] = *(const float4*)&x[(size_t)(m0 + r) * CC + k0n + c4 * 4];
            }
            #pragma unroll
            for (int i = 0; i < 2; i++) {
                int idx = tid + i * 256;
                int r = idx >> 3, c8 = idx & 7;
                brh[i] = *(const uint4*)&wth[(size_t)r * CC + k0n + c8 * 8];
                brl[i] = *(const uint4*)&wtl[(size_t)r * CC + k0n + c8 * 8];
            }
        }

        // ---- MMAs on current smem tiles
        #pragma unroll
        for (int ks = 0; ks < 4; ks++) {
            const int kk = ks * 16;
            uint32_t ah[2][4], al[2][4], bh[4][2], bl[4][2];
            #pragma unroll
            for (int mb = 0; mb < 2; mb++) {
                const uint16_t* A0h = Ahi + (mw + mb * 16) * ASTR + kk;
                const uint16_t* A0l = Alo + (mw + mb * 16) * ASTR + kk;
                ah[mb][0] = *(const uint32_t*)(A0h + g * ASTR + 2 * t);
                ah[mb][1] = *(const uint32_t*)(A0h + (g + 8) * ASTR + 2 * t);
                ah[mb][2] = *(const uint32_t*)(A0h + g * ASTR + 2 * t + 8);
                ah[mb][3] = *(const uint32_t*)(A0h + (g + 8) * ASTR + 2 * t + 8);
                al[mb][0] = *(const uint32_t*)(A0l + g * ASTR + 2 * t);
                al[mb][1] = *(const uint32_t*)(A0l + (g + 8) * ASTR + 2 * t);
                al[mb][2] = *(const uint32_t*)(A0l + g * ASTR + 2 * t + 8);
                al[mb][3] = *(const uint32_t*)(A0l + (g + 8) * ASTR + 2 * t + 8);
            }
            #pragma unroll
            for (int nb = 0; nb < 4; nb++) {
                const uint16_t* B0h = Bhi + (nw + nb * 8 + g) * ASTR + kk;
                const uint16_t* B0l = Blo + (nw + nb * 8 + g) * ASTR + kk;
                bh[nb][0] = *(const uint32_t*)(B0h + 2 * t);
                bh[nb][1] = *(const uint32_t*)(B0h + 2 * t + 8);
                bl[nb][0] = *(const uint32_t*)(B0l + 2 * t);
                bl[nb][1] = *(const uint32_t*)(B0l + 2 * t + 8);
            }
            #pragma unroll
            for (int mb = 0; mb < 2; mb++)
                #pragma unroll
                for (int nb = 0; nb < 4; nb++) {
                    mma_bf16(c[mb][nb], ah[mb], bh[nb]);
                    mma_bf16(c[mb][nb], ah[mb], bl[nb]);
                    mma_bf16(c[mb][nb], al[mb], bh[nb]);
                }
        }
        __syncthreads();
    }

    // Epilogue -> bf16 hi/lo
    #pragma unroll
    for (int mb = 0; mb < 2; mb++) {
        const int r0 = m0 + mw + mb * 16 + g;
        const int r1 = r0 + 8;
        #pragma unroll
        for (int nb = 0; nb < 4; nb++) {
            const int col = nw + nb * 8 + 2 * t;
            float v00 = c[mb][nb][0], v01 = c[mb][nb][1];
            float v10 = c[mb][nb][2], v11 = c[mb][nb][3];
            uint32_t h0 = packbf(v00, v01);
            uint32_t h1 = packbf(v10, v11);
            __nv_bfloat162 h0b = *(__nv_bfloat162*)&h0;
            __nv_bfloat162 h1b = *(__nv_bfloat162*)&h1;
            uint32_t l0 = packbf(v00 - __bfloat162float(h0b.x), v01 - __bfloat162float(h0b.y));
            uint32_t l1 = packbf(v10 - __bfloat162float(h1b.x), v11 - __bfloat162float(h1b.y));
            if (mat == 0) {
                *(uint32_t*)&g_qhi[(size_t)r0 * HH + col] = h0;
                *(uint32_t*)&g_qlo[(size_t)r0 * HH + col] = l0;
                *(uint32_t*)&g_qhi[(size_t)r1 * HH + col] = h1;
                *(uint32_t*)&g_qlo[(size_t)r1 * HH + col] = l1;
            } else if (mat == 1) {
                *(uint32_t*)&g_khi[(size_t)r0 * HH + col] = h0;
                *(uint32_t*)&g_klo[(size_t)r0 * HH + col] = l0;
                *(uint32_t*)&g_khi[(size_t)r1 * HH + col] = h1;
                *(uint32_t*)&g_klo[(size_t)r1 * HH + col] = l1;
            } else {
                __nv_bfloat162 l0b = *(__nv_bfloat162*)&l0;
                __nv_bfloat162 l1b = *(__nv_bfloat162*)&l1;
                g_vthi[(size_t)col * MM + r0]       = h0b.x;
                g_vthi[(size_t)(col + 1) * MM + r0] = h0b.y;
                g_vthi[(size_t)col * MM + r1]       = h1b.x;
                g_vthi[(size_t)(col + 1) * MM + r1] = h1b.y;
                g_vtlo[(size_t)col * MM + r0]       = l0b.x;
                g_vtlo[(size_t)(col + 1) * MM + r0] = l0b.y;
                g_vtlo[(size_t)col * MM + r1]       = l1b.x;
                g_vtlo[(size_t)(col + 1) * MM + r1] = l1b.y;
            }
        }
    }
}

// ---------------------------------------------------------------------------
// Kernel: causal flash attention, mma.sync bf16 3-pass, split-K=2,
// cp.async DOUBLE-BUFFERED K/V pipeline.
// grid = (16, 8, 2), block = 256 (8 warps x m16 = 128 queries/CTA).
// Smem: 2 stages x {Khi,Klo,Vthi,Vtlo}[64][72] = 73728 B.
// ---------------------------------------------------------------------------
#define TILE_H (64 * ASTR)                      // halves per array
#define ATTN_SMEM_BYTES (2 * 4 * TILE_H * 2)    // 73728 B

__global__ __launch_bounds__(256) void attn_kernel()
{
    uint16_t* sm16 = (uint16_t*)dyn_smem;
    const uint32_t sb = smem_u32(sm16);

    const int qt    = 15 - (int)blockIdx.x;        // heavy-first
    const int b     = blockIdx.y;
    const int split = blockIdx.z;
    const int tid = threadIdx.x;
    const int w   = tid >> 5;
    const int lid = tid & 31;
    const int g   = lid >> 2;
    const int t   = lid & 3;

    const int q0      = qt * 128;
    const int rowbase = b * TT + q0;

    const int nk    = 2 * qt + 2;
    const int klo_t = split ? (qt + 1) : 0;
    const int khi_t = split ? nk : (qt + 1);

    // ---- stage Q fragments into registers (two 64-row chunks via stage-0 bufs)
    uint16_t* Sq_hi = sm16;
    uint16_t* Sq_lo = sm16 + TILE_H;
    uint32_t qh[4][4], ql[4][4];
    #pragma unroll
    for (int ch = 0; ch < 2; ch++) {
        #pragma unroll
        for (int i = 0; i < 2; i++) {
            int idx = tid + i * 256;
            int r = idx >> 3, c8 = idx & 7;
            size_t gaddr = (size_t)(rowbase + 64 * ch + r) * HH + c8 * 8;
            *(uint4*)(Sq_hi + r * ASTR + c8 * 8) = *(const uint4*)&g_qhi[gaddr];
            *(uint4*)(Sq_lo + r * ASTR + c8 * 8) = *(const uint4*)&g_qlo[gaddr];
        }
        __syncthreads();
        if ((w >> 2) == ch) {
            const int lr = (w & 3) * 16;
            #pragma unroll
            for (int ks = 0; ks < 4; ks++) {
                const uint16_t* Qh0 = Sq_hi + (lr + g) * ASTR + ks * 16;
                const uint16_t* Ql0 = Sq_lo + (lr + g) * ASTR + ks * 16;
                qh[ks][0] = *(const uint32_t*)(Qh0 + 2 * t);
                qh[ks][1] = *(const uint32_t*)(Qh0 + 8 * ASTR + 2 * t);
                qh[ks][2] = *(const uint32_t*)(Qh0 + 2 * t + 8);
                qh[ks][3] = *(const uint32_t*)(Qh0 + 8 * ASTR + 2 * t + 8);
                ql[ks][0] = *(const uint32_t*)(Ql0 + 2 * t);
                ql[ks][1] = *(const uint32_t*)(Ql0 + 8 * ASTR + 2 * t);
                ql[ks][2] = *(const uint32_t*)(Ql0 + 2 * t + 8);
                ql[ks][3] = *(const uint32_t*)(Ql0 + 8 * ASTR + 2 * t + 8);
            }
        }
        __syncthreads();
    }

    const int qrow0 = q0 + w * 16 + g;
    const int qrow1 = qrow0 + 8;

    float o[8][4] = {};
    float m0r = -1e30f, m1r = -1e30f;
    float l0r = 0.0f,   l1r = 0.0f;

    // ---- cp.async tile preloader: K[key][dim] hi/lo + Vt[dim][key] hi/lo
    auto preload = [&](int kt, int st) {
        const int kb = kt * 64;
        const uint32_t s0 = sb + (uint32_t)st * 4 * TILE_H * 2;
        #pragma unroll
        for (int i = 0; i < 2; i++) {
            int idx = tid + i * 256;
            int r = idx >> 3, c8 = idx & 7;
            uint32_t soff = (uint32_t)(r * ASTR + c8 * 8) * 2;
            size_t ka = (size_t)(b * TT + kb + r) * HH + c8 * 8;
            size_t va = (size_t)r * MM + b * TT + kb + c8 * 8;
            cp16(s0 + soff,                  &g_khi[ka]);
            cp16(s0 + TILE_H * 2 + soff,     &g_klo[ka]);
            cp16(s0 + 2 * TILE_H * 2 + soff, &g_vthi[va]);
            cp16(s0 + 3 * TILE_H * 2 + soff, &g_vtlo[va]);
        }
        CP_COMMIT();
    };

    preload(klo_t, 0);

    for (int kt = klo_t; kt < khi_t; kt++) {
        const int kb = kt * 64;
        const int st = (kt - klo_t) & 1;
        const bool more = (kt + 1 < khi_t);
        if (more) preload(kt + 1, st ^ 1);
        if (more) asm volatile("cp.async.wait_group 1;");
        else      asm volatile("cp.async.wait_group 0;");
        __syncthreads();

        uint16_t* Khi  = sm16 + st * 4 * TILE_H;
        uint16_t* Klo  = Khi + TILE_H;
        uint16_t* Vthi = Khi + 2 * TILE_H;
        uint16_t* Vtlo = Khi + 3 * TILE_H;

        // ---- S = Q K^T (3-pass hi/lo)
        float s[8][4] = {};
        #pragma unroll
        for (int ks = 0; ks < 4; ks++) {
            #pragma unroll
            for (int nb = 0; nb < 8; nb++) {
                const uint16_t* K0h = Khi + (nb * 8 + g) * ASTR + ks * 16;
                const uint16_t* K0l = Klo + (nb * 8 + g) * ASTR + ks * 16;
                uint32_t kh[2], kl[2];
                kh[0] = *(const uint32_t*)(K0h + 2 * t);
                kh[1] = *(const uint32_t*)(K0h + 2 * t + 8);
                kl[0] = *(const uint32_t*)(K0l + 2 * t);
                kl[1] = *(const uint32_t*)(K0l + 2 * t + 8);
                mma_bf16(s[nb], qh[ks], kh);
                mma_bf16(s[nb], qh[ks], kl);
                mma_bf16(s[nb], ql[ks], kh);
            }
        }

        // ---- scale + causal mask
        const bool maskTile = (kb + 63 > q0);
        #pragma unroll
        for (int nb = 0; nb < 8; nb++) {
            const int key0 = kb + nb * 8 + 2 * t;
            s[nb][0] *= 0.125f; s[nb][1] *= 0.125f;
            s[nb][2] *= 0.125f; s[nb][3] *= 0.125f;
            if (maskTile) {
                if (key0     > qrow0) s[nb][0] = -1e38f;
                if (key0 + 1 > qrow0) s[nb][1] = -1e38f;
                if (key0     > qrow1) s[nb][2] = -1e38f;
                if (key0 + 1 > qrow1) s[nb][3] = -1e38f;
            }
        }

        // ---- online softmax (rows g and g+8), reduce over 4-lane t-group
        float mx0 = -1e38f, mx1 = -1e38f;
        #pragma unroll
        for (int nb = 0; nb < 8; nb++) {
            mx0 = fmaxf(mx0, fmaxf(s[nb][0], s[nb][1]));
            mx1 = fmaxf(mx1, fmaxf(s[nb][2], s[nb][3]));
        }
        mx0 = fmaxf(mx0, __shfl_xor_sync(0xffffffffu, mx0, 1));
        mx0 = fmaxf(mx0, __shfl_xor_sync(0xffffffffu, mx0, 2));
        mx1 = fmaxf(mx1, __shfl_xor_sync(0xffffffffu, mx1, 1));
        mx1 = fmaxf(mx1, __shfl_xor_sync(0xffffffffu, mx1, 2));

        const float nm0 = fmaxf(m0r, mx0);
        const float nm1 = fmaxf(m1r, mx1);
        const float al0 = __expf(m0r - nm0);
        const float al1 = __expf(m1r - nm1);
        float sum0 = 0.0f, sum1 = 0.0f;
        #pragma unroll
        for (int nb = 0; nb < 8; nb++) {
            s[nb][0] = __expf(s[nb][0] - nm0);
            s[nb][1] = __expf(s[nb][1] - nm0);
            s[nb][2] = __expf(s[nb][2] - nm1);
            s[nb][3] = __expf(s[nb][3] - nm1);
            sum0 += s[nb][0] + s[nb][1];
            sum1 += s[nb][2] + s[nb][3];
        }
        sum0 += __shfl_xor_sync(0xffffffffu, sum0, 1);
        sum0 += __shfl_xor_sync(0xffffffffu, sum0, 2);
        sum1 += __shfl_xor_sync(0xffffffffu, sum1, 1);
        sum1 += __shfl_xor_sync(0xffffffffu, sum1, 2);
        l0r = l0r * al0 + sum0;  m0r = nm0;
        l1r = l1r * al1 + sum1;  m1r = nm1;
        #pragma unroll
        for (int nb = 0; nb < 8; nb++) {
            o[nb][0] *= al0; o[nb][1] *= al0;
            o[nb][2] *= al1; o[nb][3] *= al1;
        }

        // ---- O += P V (P from registers, 3-pass hi/lo)
        #pragma unroll
        for (int ks = 0; ks < 4; ks++) {
            float p00 = s[2 * ks][0],     p01 = s[2 * ks][1];
            float p02 = s[2 * ks][2],     p03 = s[2 * ks][3];
            float p10 = s[2 * ks + 1][0], p11 = s[2 * ks + 1][1];
            float p12 = s[2 * ks + 1][2], p13 = s[2 * ks + 1][3];
            uint32_t aPh[4], aPl[4];
            aPh[0] = packbf(p00, p01);
            aPh[1] = packbf(p02, p03);
            aPh[2] = packbf(p10, p11);
            aPh[3] = packbf(p12, p13);
            __nv_bfloat162 b0 = *(__nv_bfloat162*)&aPh[0];
            __nv_bfloat162 b1 = *(__nv_bfloat162*)&aPh[1];
            __nv_bfloat162 b2 = *(__nv_bfloat162*)&aPh[2];
            __nv_bfloat162 b3 = *(__nv_bfloat162*)&aPh[3];
            aPl[0] = packbf(p00 - __bfloat162float(b0.x), p01 - __bfloat162float(b0.y));
            aPl[1] = packbf(p02 - __bfloat162float(b1.x), p03 - __bfloat162float(b1.y));
            aPl[2] = packbf(p10 - __bfloat162float(b2.x), p11 - __bfloat162float(b2.y));
            aPl[3] = packbf(p12 - __bfloat162float(b3.x), p13 - __bfloat162float(b3.y));
            #pragma unroll
            for (int nb = 0; nb < 8; nb++) {
                const uint16_t* V0h = Vthi + (nb * 8 + g) * ASTR + ks * 16;
                const uint16_t* V0l = Vtlo + (nb * 8 + g) * ASTR + ks * 16;
                uint32_t vh[2], vl[2];
                vh[0] = *(const uint32_t*)(V0h + 2 * t);
                vh[1] = *(const uint32_t*)(V0h + 2 * t + 8);
                vl[0] = *(const uint32_t*)(V0l + 2 * t);
                vl[1] = *(const uint32_t*)(V0l + 2 * t + 8);
                mma_bf16(o[nb], aPh, vh);
                mma_bf16(o[nb], aPh, vl);
                mma_bf16(o[nb], aPl, vh);
            }
        }
        __syncthreads();   // all warps done with stage st before it is refilled
    }

    // ---- write unnormalized O + stats
    float* Oout = g_os[split];
    const size_t ob0 = (size_t)(rowbase + w * 16 + g) * HH;
    const size_t ob1 = (size_t)(rowbase + w * 16 + g + 8) * HH;
    #pragma unroll
    for (int nb = 0; nb < 8; nb++) {
        const int col = nb * 8 + 2 * t;
        *(float2*)&Oout[ob0 + col] = make_float2(o[nb][0], o[nb][1]);
        *(float2*)&Oout[ob1 + col] = make_float2(o[nb][2], o[nb][3]);
    }
    if (t == 0) {
        g_mstat[split][rowbase + w * 16 + g]     = m0r;
        g_lstat[split][rowbase + w * 16 + g]     = l0r;
        g_mstat[split][rowbase + w * 16 + g + 8] = m1r;
        g_lstat[split][rowbase + w * 16 + g + 8] = l1r;
    }
}

// ---------------------------------------------------------------------------
// Kernel: merge the two splits.  grid = MM*HH/4/256 = 1024, block 256.
// ---------------------------------------------------------------------------
__global__ __launch_bounds__(256) void merge_kernel(float* __restrict__ out)
{
    int gid = blockIdx.x * 256 + threadIdx.x;
    int row = gid >> 4;
    float m0 = g_mstat[0][row], m1 = g_mstat[1][row];
    float l0 = g_lstat[0][row], l1 = g_lstat[1][row];
    float M  = fmaxf(m0, m1);
    float w0 = __expf(m0 - M);
    float w1 = __expf(m1 - M);
    float inv = 1.0f / (w0 * l0 + w1 * l1);
    float4 a = ((const float4*)g_os[0])[gid];
    float4 b = ((const float4*)g_os[1])[gid];
    float4 r;
    r.x = (w0 * a.x + w1 * b.x) * inv;
    r.y = (w0 * a.y + w1 * b.y) * inv;
    r.z = (w0 * a.z + w1 * b.z) * inv;
    r.w = (w0 * a.w + w1 * b.w) * inv;
    ((float4*)out)[gid] = r;
}

// ---------------------------------------------------------------------------
extern "C" void kernel_launch(void* const* d_in, const int* in_sizes, int n_in,
                              void* d_out, int out_size)
{
    const float* x  = (const float*)d_in[0];
    const float* Wq = (const float*)d_in[1];
    const float* Wk = (const float*)d_in[2];
    const float* Wv = (const float*)d_in[3];
    float* out = (float*)d_out;
    (void)in_sizes; (void)n_in; (void)out_size;

    cudaFuncSetAttribute(proj_mma_kernel, cudaFuncAttributeMaxDynamicSharedMemorySize,
                         PROJ_SMEM_BYTES);
    cudaFuncSetAttribute(attn_kernel, cudaFuncAttributeMaxDynamicSharedMemorySize,
                         ATTN_SMEM_BYTES);

    convert_w_kernel<<<3 * CC * HH / 256, 256>>>(Wq, Wk, Wv);

    dim3 ggrid(MM / 128, 3);
    proj_mma_kernel<<<ggrid, 256, PROJ_SMEM_BYTES>>>(x);

    dim3 agrid(16, BB, 2);
    attn_kernel<<<agrid, 256, ATTN_SMEM_BYTES>>>();

    merge_kernel<<<MM * HH / 4 / 256, 256>>>(out);
}